// round 1
// baseline (speedup 1.0000x reference)
#include <cuda_runtime.h>
#include <math.h>

#define Nn 100000
#define Ee 3200000
#define FIN 512
#define NHID 64
#define NCLS 40
#define KSTEPS 10

// ---------------- scratch (static device globals — no allocation) ----------
__device__ float4 g_h [Nn * 10];   // teleport term, [N][40] as float4[N][10]
__device__ float4 g_xa[Nn * 10];   // ping
__device__ float4 g_xb[Nn * 10];   // pong
__device__ int    g_counts[Nn];
__device__ int    g_rowptr[Nn + 1];
__device__ int    g_cursor[Nn];
__device__ int    g_col[Ee];
__device__ float  g_val[Ee];

// ---------------- fused 2-layer MLP: h = relu(X@W1+b1)@W2+b2 --------------
#define BM   64
#define BK   32
#define ASLD 68   // padded leading dim: 68*4B=272B, 16B-aligned rows, low bank conflicts

__global__ __launch_bounds__(256, 2)
void mlp_kernel(const float* __restrict__ feat,
                const float* __restrict__ W1, const float* __restrict__ b1,
                const float* __restrict__ W2, const float* __restrict__ b2)
{
    __shared__ __align__(16) float As [BK * ASLD];     // A^T tile: As[k][r]
    __shared__ __align__(16) float Bs [BK * NHID];     // W1 tile: Bs[k][n]
    __shared__ __align__(16) float X1s[BM * ASLD];     // layer-1 output tile
    __shared__ float W2s[NHID * NCLS];
    __shared__ float b2s[NCLS];

    const int tid = threadIdx.x;
    const int tx  = tid & 15;        // 16 col-threads
    const int ty  = tid >> 4;        // 16 row-threads
    const int row0 = blockIdx.x * BM;

    float acc[4][4];
#pragma unroll
    for (int i = 0; i < 4; i++)
#pragma unroll
        for (int j = 0; j < 4; j++) acc[i][j] = 0.f;

    for (int k0 = 0; k0 < FIN; k0 += BK) {
        // load A tile (64 rows x 32 cols), transposed into As[k][r]
#pragma unroll
        for (int j = 0; j < 2; j++) {
            int f4 = tid + j * 256;          // 0..511
            int r  = f4 >> 3;                // row within tile
            int cv = f4 & 7;                 // float4 col index
            int grow = row0 + r;
            float4 v = make_float4(0.f, 0.f, 0.f, 0.f);
            if (grow < Nn)
                v = *(const float4*)&feat[(size_t)grow * FIN + k0 + cv * 4];
            As[(cv * 4 + 0) * ASLD + r] = v.x;
            As[(cv * 4 + 1) * ASLD + r] = v.y;
            As[(cv * 4 + 2) * ASLD + r] = v.z;
            As[(cv * 4 + 3) * ASLD + r] = v.w;
        }
        // load W1 tile: 32x64 contiguous
#pragma unroll
        for (int j = 0; j < 2; j++) {
            int f4 = tid + j * 256;
            ((float4*)Bs)[f4] = ((const float4*)(W1 + (size_t)k0 * NHID))[f4];
        }
        __syncthreads();

#pragma unroll
        for (int kk = 0; kk < BK; kk++) {
            float4 a = *(const float4*)(As + kk * ASLD + ty * 4);
            float4 b = *(const float4*)(Bs + kk * NHID + tx * 4);
            float av[4] = {a.x, a.y, a.z, a.w};
            float bv[4] = {b.x, b.y, b.z, b.w};
#pragma unroll
            for (int i = 0; i < 4; i++)
#pragma unroll
                for (int j = 0; j < 4; j++)
                    acc[i][j] = fmaf(av[i], bv[j], acc[i][j]);
        }
        __syncthreads();
    }

    // layer-1 epilogue: bias + relu into smem
#pragma unroll
    for (int i = 0; i < 4; i++)
#pragma unroll
        for (int j = 0; j < 4; j++) {
            float v = acc[i][j] + __ldg(&b1[tx * 4 + j]);
            X1s[(ty * 4 + i) * ASLD + tx * 4 + j] = fmaxf(v, 0.f);
        }
    for (int i = tid; i < NHID * NCLS; i += 256) W2s[i] = W2[i];
    if (tid < NCLS) b2s[tid] = b2[tid];
    __syncthreads();

    // layer 2: each thread does one row (tid/4) x 10 cols ((tid%4)*10)
    {
        int r2 = tid >> 2;
        int c0 = (tid & 3) * 10;
        int grow = row0 + r2;
        if (grow < Nn) {
            float out[10];
#pragma unroll
            for (int c = 0; c < 10; c++) out[c] = b2s[c0 + c];
#pragma unroll 8
            for (int k = 0; k < NHID; k++) {
                float xv = X1s[r2 * ASLD + k];
#pragma unroll
                for (int c = 0; c < 10; c++)
                    out[c] = fmaf(xv, W2s[k * NCLS + c0 + c], out[c]);
            }
            float* hptr = (float*)g_h;
#pragma unroll
            for (int c = 0; c < 10; c++)
                hptr[(size_t)grow * NCLS + c0 + c] = out[c];
        }
    }
}

// ---------------- CSR build ------------------------------------------------
__global__ void zero_counts_kernel()
{
    int i = blockIdx.x * blockDim.x + threadIdx.x;
    if (i < Nn) g_counts[i] = 0;
}

__global__ void hist_kernel(const int* __restrict__ rows)
{
    int i = blockIdx.x * blockDim.x + threadIdx.x;
    if (i < Ee) atomicAdd(&g_counts[rows[i]], 1);
}

__global__ __launch_bounds__(1024)
void scan_kernel()   // single block, exclusive scan of g_counts into g_rowptr/g_cursor
{
    __shared__ int ssum[1024];
    const int T = 1024;
    int t = threadIdx.x;
    const int chunk = (Nn + T - 1) / T;
    int begin = t * chunk;
    int end   = min(begin + chunk, Nn);
    int s = 0;
    for (int i = begin; i < end; i++) s += g_counts[i];
    ssum[t] = s;
    __syncthreads();
    for (int off = 1; off < T; off <<= 1) {
        int v = (t >= off) ? ssum[t - off] : 0;
        __syncthreads();
        ssum[t] += v;
        __syncthreads();
    }
    int run = (t == 0) ? 0 : ssum[t - 1];
    for (int i = begin; i < end; i++) {
        g_rowptr[i] = run;
        g_cursor[i] = run;
        run += g_counts[i];
    }
    if (t == T - 1) g_rowptr[Nn] = run;
}

__global__ void scatter_kernel(const int* __restrict__ rows,
                               const int* __restrict__ cols,
                               const float* __restrict__ vals)
{
    int i = blockIdx.x * blockDim.x + threadIdx.x;
    if (i < Ee) {
        int r = rows[i];
        int p = atomicAdd(&g_cursor[r], 1);
        g_col[p] = cols[i];
        g_val[p] = vals[i];
    }
}

// ---------------- propagation: x_out = 0.9 * A x_in + 0.1 * h --------------
// thread t handles (node = t/10, float4 group g = t%10)
__global__ __launch_bounds__(256)
void prop_kernel(int step)
{
    const float4* __restrict__ xin =
        (step == 0) ? g_h : ((step & 1) ? g_xa : g_xb);
    float4* __restrict__ xout = (step & 1) ? g_xb : g_xa;

    int t = blockIdx.x * blockDim.x + threadIdx.x;
    if (t >= Nn * 10) return;
    int node = t / 10;
    int g    = t - node * 10;

    int s = g_rowptr[node];
    int e = g_rowptr[node + 1];
    float4 acc = make_float4(0.f, 0.f, 0.f, 0.f);
#pragma unroll 4
    for (int i = s; i < e; i++) {
        int   c = g_col[i];
        float v = g_val[i];
        float4 xv = __ldg(&xin[(size_t)c * 10 + g]);
        acc.x = fmaf(v, xv.x, acc.x);
        acc.y = fmaf(v, xv.y, acc.y);
        acc.z = fmaf(v, xv.z, acc.z);
        acc.w = fmaf(v, xv.w, acc.w);
    }
    float4 hv = g_h[t];
    float4 o;
    o.x = fmaf(0.9f, acc.x, 0.1f * hv.x);
    o.y = fmaf(0.9f, acc.y, 0.1f * hv.y);
    o.z = fmaf(0.9f, acc.z, 0.1f * hv.z);
    o.w = fmaf(0.9f, acc.w, 0.1f * hv.w);
    xout[t] = o;
}

// ---------------- log_softmax: warp per node -------------------------------
__global__ __launch_bounds__(256)
void logsoftmax_kernel(float* __restrict__ out)
{
    const float* __restrict__ x = (const float*)g_xb;   // step 9 output lives in g_xb
    int warp = (blockIdx.x * blockDim.x + threadIdx.x) >> 5;
    int lane = threadIdx.x & 31;
    if (warp >= Nn) return;
    const float* xr = x + (size_t)warp * NCLS;
    float v0 = xr[lane];
    float v1 = (lane < 8) ? xr[32 + lane] : -INFINITY;
    float m = fmaxf(v0, v1);
#pragma unroll
    for (int off = 16; off > 0; off >>= 1)
        m = fmaxf(m, __shfl_xor_sync(0xffffffffu, m, off));
    float s = expf(v0 - m) + ((lane < 8) ? expf(v1 - m) : 0.f);
#pragma unroll
    for (int off = 16; off > 0; off >>= 1)
        s += __shfl_xor_sync(0xffffffffu, s, off);
    float lse = m + logf(s);
    float* o = out + (size_t)warp * NCLS;
    o[lane] = v0 - lse;
    if (lane < 8) o[32 + lane] = v1 - lse;
}

// ---------------- launch ---------------------------------------------------
extern "C" void kernel_launch(void* const* d_in, const int* in_sizes, int n_in,
                              void* d_out, int out_size)
{
    const float* feat = (const float*)d_in[0];
    const int*   ei   = (const int*)  d_in[1];
    const float* ev   = (const float*)d_in[2];
    const float* W1   = (const float*)d_in[3];
    const float* b1   = (const float*)d_in[4];
    const float* W2   = (const float*)d_in[5];
    const float* b2   = (const float*)d_in[6];
    const int* rows = ei;
    const int* cols = ei + Ee;

    // MLP (independent of CSR build)
    mlp_kernel<<<(Nn + BM - 1) / BM, 256>>>(feat, W1, b1, W2, b2);

    // CSR build
    zero_counts_kernel<<<(Nn + 255) / 256, 256>>>();
    hist_kernel<<<(Ee + 255) / 256, 256>>>(rows);
    scan_kernel<<<1, 1024>>>();
    scatter_kernel<<<(Ee + 255) / 256, 256>>>(rows, cols, ev);

    // 10 propagation steps (h -> xa -> xb -> ... -> xb)
    int pthreads = Nn * 10;
    int pblocks  = (pthreads + 255) / 256;
    for (int s = 0; s < KSTEPS; s++)
        prop_kernel<<<pblocks, 256>>>(s);

    // log_softmax over final buffer (g_xb)
    int lthreads = Nn * 32;
    logsoftmax_kernel<<<(lthreads + 255) / 256, 256>>>((float*)d_out);
}

// round 2
// speedup vs baseline: 1.3079x; 1.3079x over previous
#include <cuda_runtime.h>
#include <math.h>

#define Nn 100000
#define Ee 3200000
#define FIN 512
#define NHID 64
#define NCLS 40
#define KSTEPS 10

// ---------------- scratch (static device globals — no allocation) ----------
__device__ float4 g_h [Nn * 10];   // teleport term, [N][40] as float4[N][10]
__device__ float4 g_xa[Nn * 10];   // ping
__device__ float4 g_xb[Nn * 10];   // pong
__device__ int    g_counts[Nn];
__device__ int    g_rowptr[Nn + 1];
__device__ int    g_cursor[Nn];
__device__ int    g_col[Ee];
__device__ float  g_val[Ee];

#define SCAN_BLK  1024
#define SCAN_NBLK ((Nn + SCAN_BLK - 1) / SCAN_BLK)   // 98
__device__ int    g_bsums[SCAN_NBLK];
__device__ int    g_boffs[SCAN_NBLK + 1];

// ---------------- fused 2-layer MLP: h = relu(X@W1+b1)@W2+b2 --------------
// 64x64 output tile, 128 threads, 8x4 register blocking.
#define BM   64
#define BK   32
#define ASLD 68   // padded leading dim

__global__ __launch_bounds__(128)
void mlp_kernel(const float* __restrict__ feat,
                const float* __restrict__ W1, const float* __restrict__ b1,
                const float* __restrict__ W2, const float* __restrict__ b2)
{
    __shared__ __align__(16) float As [BK * ASLD];     // A^T tile: As[k][r]
    __shared__ __align__(16) float Bs [BK * NHID];     // W1 tile: Bs[k][n]
    __shared__ __align__(16) float X1s[BM * ASLD];     // layer-1 output tile
    __shared__ float W2s[NHID * NCLS];
    __shared__ float b2s[NCLS];

    const int tid = threadIdx.x;
    const int tx  = tid & 15;        // 16 col-groups of 4 cols
    const int ty  = tid >> 4;        // 8 row-groups of 8 rows
    const int row0 = blockIdx.x * BM;

    float acc[8][4];
#pragma unroll
    for (int i = 0; i < 8; i++)
#pragma unroll
        for (int j = 0; j < 4; j++) acc[i][j] = 0.f;

    for (int k0 = 0; k0 < FIN; k0 += BK) {
        // load A tile (64 rows x 32 cols), transposed into As[k][r]
#pragma unroll
        for (int j = 0; j < 4; j++) {
            int f4 = tid + j * 128;          // 0..511
            int r  = f4 >> 3;                // row within tile (0..63)
            int cv = f4 & 7;                 // float4 col index (0..7)
            int grow = row0 + r;
            float4 v = make_float4(0.f, 0.f, 0.f, 0.f);
            if (grow < Nn)
                v = *(const float4*)&feat[(size_t)grow * FIN + k0 + cv * 4];
            As[(cv * 4 + 0) * ASLD + r] = v.x;
            As[(cv * 4 + 1) * ASLD + r] = v.y;
            As[(cv * 4 + 2) * ASLD + r] = v.z;
            As[(cv * 4 + 3) * ASLD + r] = v.w;
        }
        // load W1 tile: 32x64 contiguous (512 float4)
#pragma unroll
        for (int j = 0; j < 4; j++) {
            int f4 = tid + j * 128;
            ((float4*)Bs)[f4] = ((const float4*)(W1 + (size_t)k0 * NHID))[f4];
        }
        __syncthreads();

#pragma unroll
        for (int kk = 0; kk < BK; kk++) {
            float4 a0 = *(const float4*)(As + kk * ASLD + ty * 8);
            float4 a1 = *(const float4*)(As + kk * ASLD + ty * 8 + 4);
            float4 b  = *(const float4*)(Bs + kk * NHID + tx * 4);
            float av[8] = {a0.x, a0.y, a0.z, a0.w, a1.x, a1.y, a1.z, a1.w};
            float bv[4] = {b.x, b.y, b.z, b.w};
#pragma unroll
            for (int i = 0; i < 8; i++)
#pragma unroll
                for (int j = 0; j < 4; j++)
                    acc[i][j] = fmaf(av[i], bv[j], acc[i][j]);
        }
        __syncthreads();
    }

    // layer-1 epilogue: bias + relu into smem
#pragma unroll
    for (int i = 0; i < 8; i++)
#pragma unroll
        for (int j = 0; j < 4; j++) {
            float v = acc[i][j] + __ldg(&b1[tx * 4 + j]);
            X1s[(ty * 8 + i) * ASLD + tx * 4 + j] = fmaxf(v, 0.f);
        }
    for (int i = tid; i < NHID * NCLS; i += 128) W2s[i] = W2[i];
    if (tid < NCLS) b2s[tid] = b2[tid];
    __syncthreads();

    // layer 2: each thread does one row (tid/2) x 20 cols ((tid%2)*20)
    {
        int r2 = tid >> 1;
        int c0 = (tid & 1) * 20;
        int grow = row0 + r2;
        if (grow < Nn) {
            float out[20];
#pragma unroll
            for (int c = 0; c < 20; c++) out[c] = b2s[c0 + c];
#pragma unroll 4
            for (int k = 0; k < NHID; k++) {
                float xv = X1s[r2 * ASLD + k];
#pragma unroll
                for (int c = 0; c < 20; c++)
                    out[c] = fmaf(xv, W2s[k * NCLS + c0 + c], out[c]);
            }
            float* hptr = (float*)g_h;
#pragma unroll
            for (int c = 0; c < 20; c++)
                hptr[(size_t)grow * NCLS + c0 + c] = out[c];
        }
    }
}

// ---------------- CSR build ------------------------------------------------
__global__ void zero_counts_kernel()
{
    int i = blockIdx.x * blockDim.x + threadIdx.x;
    if (i < Nn) g_counts[i] = 0;
}

__global__ void hist_kernel(const int* __restrict__ rows)
{
    int i = blockIdx.x * blockDim.x + threadIdx.x;
    if (i < Ee) atomicAdd(&g_counts[rows[i]], 1);
}

// pass 1: per-block exclusive scan (local), block totals to g_bsums
__global__ __launch_bounds__(SCAN_BLK)
void scan1_kernel()
{
    __shared__ int swarp[32];
    int t = threadIdx.x;
    int i = blockIdx.x * SCAN_BLK + t;
    int lane = t & 31, wid = t >> 5;

    int v = (i < Nn) ? g_counts[i] : 0;
    // warp inclusive scan
    int incl = v;
#pragma unroll
    for (int off = 1; off < 32; off <<= 1) {
        int u = __shfl_up_sync(0xffffffffu, incl, off);
        if (lane >= off) incl += u;
    }
    if (lane == 31) swarp[wid] = incl;
    __syncthreads();
    if (wid == 0) {
        int w = swarp[lane];
        int wi = w;
#pragma unroll
        for (int off = 1; off < 32; off <<= 1) {
            int u = __shfl_up_sync(0xffffffffu, wi, off);
            if (lane >= off) wi += u;
        }
        swarp[lane] = wi - w;     // exclusive warp offsets
        if (lane == 31 && blockIdx.x < SCAN_NBLK) g_bsums[blockIdx.x] = wi;
    }
    __syncthreads();
    if (i < Nn) g_rowptr[i] = incl - v + swarp[wid];   // local exclusive
}

// pass 2: scan the 98 block sums (single block)
__global__ __launch_bounds__(128)
void scan2_kernel()
{
    __shared__ int s[SCAN_NBLK];
    int t = threadIdx.x;
    if (t < SCAN_NBLK) s[t] = g_bsums[t];
    __syncthreads();
    if (t == 0) {
        int run = 0;
        for (int b = 0; b < SCAN_NBLK; b++) {
            g_boffs[b] = run;
            run += s[b];
        }
        g_boffs[SCAN_NBLK] = run;
        g_rowptr[Nn] = run;
    }
}

// pass 3: add block offsets, fill cursor
__global__ __launch_bounds__(SCAN_BLK)
void scan3_kernel()
{
    int i = blockIdx.x * SCAN_BLK + threadIdx.x;
    if (i < Nn) {
        int r = g_rowptr[i] + g_boffs[blockIdx.x];
        g_rowptr[i] = r;
        g_cursor[i] = r;
    }
}

__global__ void scatter_kernel(const int* __restrict__ rows,
                               const int* __restrict__ cols,
                               const float* __restrict__ vals)
{
    int i = blockIdx.x * blockDim.x + threadIdx.x;
    if (i < Ee) {
        int r = rows[i];
        int p = atomicAdd(&g_cursor[r], 1);
        g_col[p] = cols[i];
        g_val[p] = vals[i];
    }
}

// ---------------- propagation: x_out = 0.9 * A x_in + 0.1 * h --------------
// thread t handles (node = t/10, float4 group g = t%10)
__global__ __launch_bounds__(256)
void prop_kernel(int step)
{
    const float4* __restrict__ xin =
        (step == 0) ? g_h : ((step & 1) ? g_xa : g_xb);
    float4* __restrict__ xout = (step & 1) ? g_xb : g_xa;

    int t = blockIdx.x * blockDim.x + threadIdx.x;
    if (t >= Nn * 10) return;
    int node = t / 10;
    int g    = t - node * 10;

    int s = g_rowptr[node];
    int e = g_rowptr[node + 1];
    float4 acc = make_float4(0.f, 0.f, 0.f, 0.f);
#pragma unroll 4
    for (int i = s; i < e; i++) {
        int   c = g_col[i];
        float v = g_val[i];
        float4 xv = __ldg(&xin[(size_t)c * 10 + g]);
        acc.x = fmaf(v, xv.x, acc.x);
        acc.y = fmaf(v, xv.y, acc.y);
        acc.z = fmaf(v, xv.z, acc.z);
        acc.w = fmaf(v, xv.w, acc.w);
    }
    float4 hv = g_h[t];
    float4 o;
    o.x = fmaf(0.9f, acc.x, 0.1f * hv.x);
    o.y = fmaf(0.9f, acc.y, 0.1f * hv.y);
    o.z = fmaf(0.9f, acc.z, 0.1f * hv.z);
    o.w = fmaf(0.9f, acc.w, 0.1f * hv.w);
    xout[t] = o;
}

// ---------------- log_softmax: warp per node -------------------------------
__global__ __launch_bounds__(256)
void logsoftmax_kernel(float* __restrict__ out)
{
    const float* __restrict__ x = (const float*)g_xb;   // step 9 output lives in g_xb
    int warp = (blockIdx.x * blockDim.x + threadIdx.x) >> 5;
    int lane = threadIdx.x & 31;
    if (warp >= Nn) return;
    const float* xr = x + (size_t)warp * NCLS;
    float v0 = xr[lane];
    float v1 = (lane < 8) ? xr[32 + lane] : -INFINITY;
    float m = fmaxf(v0, v1);
#pragma unroll
    for (int off = 16; off > 0; off >>= 1)
        m = fmaxf(m, __shfl_xor_sync(0xffffffffu, m, off));
    float s = expf(v0 - m) + ((lane < 8) ? expf(v1 - m) : 0.f);
#pragma unroll
    for (int off = 16; off > 0; off >>= 1)
        s += __shfl_xor_sync(0xffffffffu, s, off);
    float lse = m + logf(s);
    float* o = out + (size_t)warp * NCLS;
    o[lane] = v0 - lse;
    if (lane < 8) o[32 + lane] = v1 - lse;
}

// ---------------- launch ---------------------------------------------------
extern "C" void kernel_launch(void* const* d_in, const int* in_sizes, int n_in,
                              void* d_out, int out_size)
{
    const float* feat = (const float*)d_in[0];
    const int*   ei   = (const int*)  d_in[1];
    const float* ev   = (const float*)d_in[2];
    const float* W1   = (const float*)d_in[3];
    const float* b1   = (const float*)d_in[4];
    const float* W2   = (const float*)d_in[5];
    const float* b2   = (const float*)d_in[6];
    const int* rows = ei;
    const int* cols = ei + Ee;

    // MLP
    mlp_kernel<<<(Nn + BM - 1) / BM, 128>>>(feat, W1, b1, W2, b2);

    // CSR build
    zero_counts_kernel<<<(Nn + 255) / 256, 256>>>();
    hist_kernel<<<(Ee + 255) / 256, 256>>>(rows);
    scan1_kernel<<<SCAN_NBLK, SCAN_BLK>>>();
    scan2_kernel<<<1, 128>>>();
    scan3_kernel<<<SCAN_NBLK, SCAN_BLK>>>();
    scatter_kernel<<<(Ee + 255) / 256, 256>>>(rows, cols, ev);

    // 10 propagation steps (h -> xa -> xb -> ... -> xb)
    int pthreads = Nn * 10;
    int pblocks  = (pthreads + 255) / 256;
    for (int s = 0; s < KSTEPS; s++)
        prop_kernel<<<pblocks, 256>>>(s);

    // log_softmax over final buffer (g_xb)
    int lthreads = Nn * 32;
    logsoftmax_kernel<<<(lthreads + 255) / 256, 256>>>((float*)d_out);
}

// round 3
// speedup vs baseline: 1.3100x; 1.0016x over previous
#include <cuda_runtime.h>
#include <math.h>

#define Nn 100000
#define Ee 3200000
#define FIN 512
#define NHID 64
#define NCLS 40
#define KSTEPS 10

// ---------------- scratch (static device globals — no allocation) ----------
__device__ float4 g_h [Nn * 10];   // teleport term, [N][40] as float4[N][10]
__device__ float4 g_xa[Nn * 10];   // ping
__device__ float4 g_xb[Nn * 10];   // pong
__device__ int    g_counts[Nn];
__device__ int    g_rowptr[Nn + 1];
__device__ int    g_cursor[Nn];
__device__ int2   g_colval[Ee];    // interleaved {col, val-bits}

#define SCAN_BLK  1024
#define SCAN_NBLK ((Nn + SCAN_BLK - 1) / SCAN_BLK)   // 98
__device__ unsigned long long g_pub[SCAN_NBLK];      // packed {flag,sum}

// ---------------- fused 2-layer MLP: h = relu(X@W1+b1)@W2+b2 --------------
// BM=128 x BN=64 tile, 128 threads, 8x8 register blocking, BK=16.
#define BM   128
#define BK   16
#define LDA  132   // As: [BK][BM+4]
#define LDB  68    // Bs: [BK][64+4], upper 32 cols shifted +4 floats (swizzle)
#define LDX  68    // X1s: [BM][64+4]

// phase1: As 16*132=2112 + Bs 16*68=1088 = 3200 floats
// phase2: X1s 128*68=8704 + W2s 2560 + b2s 40 = 11304 floats
#define MLP_SMEM_FLOATS 11312

__global__ __launch_bounds__(128)
void mlp_kernel(const float* __restrict__ feat,
                const float* __restrict__ W1, const float* __restrict__ b1,
                const float* __restrict__ W2, const float* __restrict__ b2)
{
    __shared__ __align__(16) float sm[MLP_SMEM_FLOATS];
    float* As  = sm;            // phase 1
    float* Bs  = sm + 2112;     // phase 1
    float* X1s = sm;            // phase 2 (reuses As/Bs space)
    float* W2s = sm + 8704;     // phase 2
    float* b2s = sm + 8704 + 2560;

    const int tid = threadIdx.x;
    const int tx  = tid & 7;         // 8 col-groups of 8 cols
    const int ty  = tid >> 3;        // 16 row-groups of 8 rows
    const int row0 = blockIdx.x * BM;
    const int boff = tx * 8 + ((tx >= 4) ? 4 : 0);   // swizzled B read offset

    float acc[8][8];
#pragma unroll
    for (int i = 0; i < 8; i++)
#pragma unroll
        for (int j = 0; j < 8; j++) acc[i][j] = 0.f;

    for (int k0 = 0; k0 < FIN; k0 += BK) {
        // As: 128 rows x 16 cols, transposed into As[k][r]. 512 float4, 4/thread.
#pragma unroll
        for (int j = 0; j < 4; j++) {
            int f4 = tid + j * 128;
            int r  = f4 >> 2;            // row in tile (0..127)
            int cv = f4 & 3;             // float4 col index (0..3)
            int grow = row0 + r;
            float4 v = make_float4(0.f, 0.f, 0.f, 0.f);
            if (grow < Nn)
                v = *(const float4*)&feat[(size_t)grow * FIN + k0 + cv * 4];
            As[(cv * 4 + 0) * LDA + r] = v.x;
            As[(cv * 4 + 1) * LDA + r] = v.y;
            As[(cv * 4 + 2) * LDA + r] = v.z;
            As[(cv * 4 + 3) * LDA + r] = v.w;
        }
        // Bs: 16 rows x 64 cols. 256 float4, 2/thread, swizzled store.
#pragma unroll
        for (int j = 0; j < 2; j++) {
            int f4 = tid + j * 128;
            int k  = f4 >> 4;            // 0..15
            int n  = (f4 & 15) * 4;      // 0..60
            float4 w = ((const float4*)(W1 + (size_t)(k0 + k) * NHID))[f4 & 15];
            *(float4*)&Bs[k * LDB + n + ((n >= 32) ? 4 : 0)] = w;
        }
        __syncthreads();

#pragma unroll
        for (int kk = 0; kk < BK; kk++) {
            float4 a0 = *(const float4*)(As + kk * LDA + ty * 8);
            float4 a1 = *(const float4*)(As + kk * LDA + ty * 8 + 4);
            float4 b0 = *(const float4*)(Bs + kk * LDB + boff);
            float4 b1v = *(const float4*)(Bs + kk * LDB + boff + 4);
            float av[8] = {a0.x, a0.y, a0.z, a0.w, a1.x, a1.y, a1.z, a1.w};
            float bv[8] = {b0.x, b0.y, b0.z, b0.w, b1v.x, b1v.y, b1v.z, b1v.w};
#pragma unroll
            for (int i = 0; i < 8; i++)
#pragma unroll
                for (int j = 0; j < 8; j++)
                    acc[i][j] = fmaf(av[i], bv[j], acc[i][j]);
        }
        __syncthreads();
    }

    // layer-1 epilogue: bias + relu into X1s (reuses As/Bs space; safe after sync)
#pragma unroll
    for (int i = 0; i < 8; i++)
#pragma unroll
        for (int j = 0; j < 8; j++) {
            float v = acc[i][j] + __ldg(&b1[tx * 8 + j]);
            X1s[(ty * 8 + i) * LDX + tx * 8 + j] = fmaxf(v, 0.f);
        }
    for (int i = tid; i < NHID * NCLS; i += 128) W2s[i] = W2[i];
    if (tid < NCLS) b2s[tid] = b2[tid];
    __syncthreads();

    // layer 2: one thread per row, 40 outputs
    {
        int grow = row0 + tid;
        if (grow < Nn) {
            float out[NCLS];
#pragma unroll
            for (int c = 0; c < NCLS; c++) out[c] = b2s[c];
#pragma unroll 4
            for (int k = 0; k < NHID; k++) {
                float xv = X1s[tid * LDX + k];
#pragma unroll
                for (int c = 0; c < NCLS; c++)
                    out[c] = fmaf(xv, W2s[k * NCLS + c], out[c]);
            }
            float4* hp = g_h + (size_t)grow * 10;
#pragma unroll
            for (int q = 0; q < 10; q++)
                hp[q] = make_float4(out[4*q], out[4*q+1], out[4*q+2], out[4*q+3]);
        }
    }
}

// ---------------- CSR build ------------------------------------------------
__global__ void zero_kernel()
{
    int i = blockIdx.x * blockDim.x + threadIdx.x;
    if (i < Nn) g_counts[i] = 0;
    if (i < SCAN_NBLK) g_pub[i] = 0ull;
}

__global__ void hist_kernel(const int* __restrict__ rows)
{
    int j = blockIdx.x * blockDim.x + threadIdx.x;
    if (j < Ee / 4) {
        int4 r = ((const int4*)rows)[j];
        atomicAdd(&g_counts[r.x], 1);
        atomicAdd(&g_counts[r.y], 1);
        atomicAdd(&g_counts[r.z], 1);
        atomicAdd(&g_counts[r.w], 1);
    }
}

// single-pass decoupled-lookback exclusive scan of g_counts -> g_rowptr/g_cursor
__global__ __launch_bounds__(SCAN_BLK)
void scan_kernel()
{
    __shared__ int swarp[32];
    __shared__ int s_prefix;
    __shared__ int s_total;

    const int b = blockIdx.x;
    const int t = threadIdx.x;
    const int lane = t & 31, wid = t >> 5;
    const int i = b * SCAN_BLK + t;

    int v = (i < Nn) ? g_counts[i] : 0;
    int incl = v;
#pragma unroll
    for (int off = 1; off < 32; off <<= 1) {
        int u = __shfl_up_sync(0xffffffffu, incl, off);
        if (lane >= off) incl += u;
    }
    if (lane == 31) swarp[wid] = incl;
    __syncthreads();
    if (wid == 0) {
        int w = swarp[lane];
        int wi = w;
#pragma unroll
        for (int off = 1; off < 32; off <<= 1) {
            int u = __shfl_up_sync(0xffffffffu, wi, off);
            if (lane >= off) wi += u;
        }
        swarp[lane] = wi - w;            // exclusive warp offsets
        if (lane == 31) {
            int S = wi;                   // block total
            s_total = S;
            if (b == 0) {
                atomicExch(&g_pub[0], (2ull << 32) | (unsigned)S);
                s_prefix = 0;
            } else {
                atomicExch(&g_pub[b], (1ull << 32) | (unsigned)S);
                long long run = 0;
                int p = b - 1;
                while (true) {
                    unsigned long long u =
                        *((volatile unsigned long long*)&g_pub[p]);
                    unsigned f = (unsigned)(u >> 32);
                    if (f == 2u) { run += (int)(unsigned)u; break; }
                    if (f == 1u) { run += (int)(unsigned)u; p--; }
                }
                atomicExch(&g_pub[b], (2ull << 32) | (unsigned)(run + S));
                s_prefix = (int)run;
            }
        }
    }
    __syncthreads();
    int pref = s_prefix;
    if (i < Nn) {
        int r = incl - v + swarp[wid] + pref;
        g_rowptr[i] = r;
        g_cursor[i] = r;
    }
    if (b == SCAN_NBLK - 1 && t == 0)
        g_rowptr[Nn] = pref + s_total;
}

__global__ void scatter_kernel(const int* __restrict__ rows,
                               const int* __restrict__ cols,
                               const float* __restrict__ vals)
{
    int j = blockIdx.x * blockDim.x + threadIdx.x;
    if (j < Ee / 4) {
        int4   r = ((const int4*)rows)[j];
        int4   c = ((const int4*)cols)[j];
        float4 v = ((const float4*)vals)[j];
        int p;
        p = atomicAdd(&g_cursor[r.x], 1); g_colval[p] = make_int2(c.x, __float_as_int(v.x));
        p = atomicAdd(&g_cursor[r.y], 1); g_colval[p] = make_int2(c.y, __float_as_int(v.y));
        p = atomicAdd(&g_cursor[r.z], 1); g_colval[p] = make_int2(c.z, __float_as_int(v.z));
        p = atomicAdd(&g_cursor[r.w], 1); g_colval[p] = make_int2(c.w, __float_as_int(v.w));
    }
}

// ---------------- propagation: x_out = 0.9 * A x_in + 0.1 * h --------------
// thread t handles (node = t/10, float4 group g = t%10)
__global__ __launch_bounds__(256)
void prop_kernel(int step)
{
    const float4* __restrict__ xin =
        (step == 0) ? g_h : ((step & 1) ? g_xa : g_xb);
    float4* __restrict__ xout = (step & 1) ? g_xb : g_xa;

    int t = blockIdx.x * blockDim.x + threadIdx.x;
    if (t >= Nn * 10) return;
    int node = t / 10;
    int g    = t - node * 10;

    int s = g_rowptr[node];
    int e = g_rowptr[node + 1];
    float4 a0 = make_float4(0.f, 0.f, 0.f, 0.f);
    float4 a1 = make_float4(0.f, 0.f, 0.f, 0.f);
    int i = s;
    for (; i + 2 <= e; i += 2) {
        int2 c0 = g_colval[i];
        int2 c1 = g_colval[i + 1];
        float4 x0 = __ldg(&xin[(size_t)c0.x * 10 + g]);
        float4 x1 = __ldg(&xin[(size_t)c1.x * 10 + g]);
        float v0 = __int_as_float(c0.y);
        float v1 = __int_as_float(c1.y);
        a0.x = fmaf(v0, x0.x, a0.x);  a1.x = fmaf(v1, x1.x, a1.x);
        a0.y = fmaf(v0, x0.y, a0.y);  a1.y = fmaf(v1, x1.y, a1.y);
        a0.z = fmaf(v0, x0.z, a0.z);  a1.z = fmaf(v1, x1.z, a1.z);
        a0.w = fmaf(v0, x0.w, a0.w);  a1.w = fmaf(v1, x1.w, a1.w);
    }
    if (i < e) {
        int2 c0 = g_colval[i];
        float4 x0 = __ldg(&xin[(size_t)c0.x * 10 + g]);
        float v0 = __int_as_float(c0.y);
        a0.x = fmaf(v0, x0.x, a0.x);
        a0.y = fmaf(v0, x0.y, a0.y);
        a0.z = fmaf(v0, x0.z, a0.z);
        a0.w = fmaf(v0, x0.w, a0.w);
    }
    float4 hv = g_h[t];
    float4 o;
    o.x = fmaf(0.9f, a0.x + a1.x, 0.1f * hv.x);
    o.y = fmaf(0.9f, a0.y + a1.y, 0.1f * hv.y);
    o.z = fmaf(0.9f, a0.z + a1.z, 0.1f * hv.z);
    o.w = fmaf(0.9f, a0.w + a1.w, 0.1f * hv.w);
    xout[t] = o;
}

// ---------------- log_softmax: warp per node -------------------------------
__global__ __launch_bounds__(256)
void logsoftmax_kernel(float* __restrict__ out)
{
    const float* __restrict__ x = (const float*)g_xb;   // step 9 output
    int warp = (blockIdx.x * blockDim.x + threadIdx.x) >> 5;
    int lane = threadIdx.x & 31;
    if (warp >= Nn) return;
    const float* xr = x + (size_t)warp * NCLS;
    float v0 = xr[lane];
    float v1 = (lane < 8) ? xr[32 + lane] : -INFINITY;
    float m = fmaxf(v0, v1);
#pragma unroll
    for (int off = 16; off > 0; off >>= 1)
        m = fmaxf(m, __shfl_xor_sync(0xffffffffu, m, off));
    float s = expf(v0 - m) + ((lane < 8) ? expf(v1 - m) : 0.f);
#pragma unroll
    for (int off = 16; off > 0; off >>= 1)
        s += __shfl_xor_sync(0xffffffffu, s, off);
    float lse = m + logf(s);
    float* o = out + (size_t)warp * NCLS;
    o[lane] = v0 - lse;
    if (lane < 8) o[32 + lane] = v1 - lse;
}

// ---------------- launch ---------------------------------------------------
extern "C" void kernel_launch(void* const* d_in, const int* in_sizes, int n_in,
                              void* d_out, int out_size)
{
    const float* feat = (const float*)d_in[0];
    const int*   ei   = (const int*)  d_in[1];
    const float* ev   = (const float*)d_in[2];
    const float* W1   = (const float*)d_in[3];
    const float* b1   = (const float*)d_in[4];
    const float* W2   = (const float*)d_in[5];
    const float* b2   = (const float*)d_in[6];
    const int* rows = ei;
    const int* cols = ei + Ee;

    zero_kernel<<<(Nn + 255) / 256, 256>>>();                       // 1
    hist_kernel<<<(Ee / 4 + 255) / 256, 256>>>(rows);               // 2
    scan_kernel<<<SCAN_NBLK, SCAN_BLK>>>();                         // 3
    mlp_kernel<<<(Nn + BM - 1) / BM, 128>>>(feat, W1, b1, W2, b2);  // 4 (profiled)
    scatter_kernel<<<(Ee / 4 + 255) / 256, 256>>>(rows, cols, ev);  // 5

    int pblocks = (Nn * 10 + 255) / 256;
    for (int s = 0; s < KSTEPS; s++)
        prop_kernel<<<pblocks, 256>>>(s);

    logsoftmax_kernel<<<(Nn * 32 + 255) / 256, 256>>>((float*)d_out);
}

// round 4
// speedup vs baseline: 1.4875x; 1.1355x over previous
#include <cuda_runtime.h>
#include <math.h>

#define Nn 100000
#define Ee 3200000
#define FIN 512
#define NHID 64
#define NCLS 40
#define KSTEPS 10

// ---------------- scratch (static device globals — no allocation) ----------
__device__ float4 g_h [Nn * 10];   // teleport term, [N][40] as float4[N][10]
__device__ float4 g_xa[Nn * 10];   // ping
__device__ float4 g_xb[Nn * 10];   // pong
__device__ float  g_x1[(size_t)Nn * NHID];  // layer-1 activations
__device__ int    g_counts[Nn];
__device__ int    g_rowptr[Nn + 1];
__device__ int    g_cursor[Nn];
__device__ int2   g_colval[Ee];    // interleaved {col, val-bits}

#define SCAN_BLK  1024
#define SCAN_NBLK ((Nn + SCAN_BLK - 1) / SCAN_BLK)   // 98
__device__ unsigned long long g_pub[SCAN_NBLK];      // packed {flag,sum}

// ---------------- layer 1: x1 = relu(X@W1 + b1) via tf32 mma ---------------
// BM=128, BN=64, BK=32. 8 warps; warp tile 32x32 = 2(m) x 4(n) m16n8k8 tiles.
#define L1_BM 128
#define L1_BK 32
#define LDA   36    // As[m][k], (36m+k)%32 = (4m+k)%32 -> conflict-free frags
#define LDB   72    // Bs[k][n], (72k+n)%32 = (8k+n)%32 -> conflict-free frags

__device__ __forceinline__ unsigned f2tf32(float f) {
    unsigned r;
    asm("cvt.rna.tf32.f32 %0, %1;" : "=r"(r) : "f"(f));
    return r;
}

__device__ __forceinline__ void mma_tf32(float* c, unsigned a0, unsigned a1,
                                         unsigned a2, unsigned a3,
                                         unsigned b0, unsigned b1) {
    asm volatile(
        "mma.sync.aligned.m16n8k8.row.col.f32.tf32.tf32.f32 "
        "{%0,%1,%2,%3}, {%4,%5,%6,%7}, {%8,%9}, {%0,%1,%2,%3};\n"
        : "+f"(c[0]), "+f"(c[1]), "+f"(c[2]), "+f"(c[3])
        : "r"(a0), "r"(a1), "r"(a2), "r"(a3), "r"(b0), "r"(b1));
}

__global__ __launch_bounds__(256, 3)
void mlp1_kernel(const float* __restrict__ feat,
                 const float* __restrict__ W1, const float* __restrict__ b1)
{
    __shared__ unsigned As[L1_BM * LDA];   // 128x36  tf32 bits
    __shared__ unsigned Bs[L1_BK * LDB];   // 32x72   tf32 bits

    const int tid    = threadIdx.x;
    const int lane   = tid & 31;
    const int warp   = tid >> 5;
    const int warp_m = warp & 3;           // 0..3  (32 rows each)
    const int warp_n = warp >> 2;          // 0..1  (32 cols each)
    const int gid    = lane >> 2;          // 0..7
    const int tig    = lane & 3;           // 0..3
    const int row0   = blockIdx.x * L1_BM;

    float acc[2][4][4];
#pragma unroll
    for (int mi = 0; mi < 2; mi++)
#pragma unroll
        for (int ni = 0; ni < 4; ni++)
#pragma unroll
            for (int q = 0; q < 4; q++) acc[mi][ni][q] = 0.f;

    for (int k0 = 0; k0 < FIN; k0 += L1_BK) {
        // stage A: 128x32 floats (1024 float4, 4 per thread), cvt to tf32
#pragma unroll
        for (int j = 0; j < 4; j++) {
            int id = tid + j * 256;
            int m  = id >> 3;
            int kc = id & 7;
            int grow = row0 + m;
            float4 v = make_float4(0.f, 0.f, 0.f, 0.f);
            if (grow < Nn)
                v = *(const float4*)&feat[(size_t)grow * FIN + k0 + kc * 4];
            unsigned* s = &As[m * LDA + kc * 4];
            s[0] = f2tf32(v.x); s[1] = f2tf32(v.y);
            s[2] = f2tf32(v.z); s[3] = f2tf32(v.w);
        }
        // stage B: 32x64 floats (512 float4, 2 per thread)
#pragma unroll
        for (int j = 0; j < 2; j++) {
            int id = tid + j * 256;
            int k  = id >> 4;
            int nc = id & 15;
            float4 w = *(const float4*)&W1[(size_t)(k0 + k) * NHID + nc * 4];
            unsigned* s = &Bs[k * LDB + nc * 4];
            s[0] = f2tf32(w.x); s[1] = f2tf32(w.y);
            s[2] = f2tf32(w.z); s[3] = f2tf32(w.w);
        }
        __syncthreads();

#pragma unroll
        for (int kk = 0; kk < L1_BK; kk += 8) {
            unsigned a[2][4], b[4][2];
#pragma unroll
            for (int mi = 0; mi < 2; mi++) {
                int m0 = warp_m * 32 + mi * 16;
                a[mi][0] = As[(m0 + gid)     * LDA + kk + tig];
                a[mi][1] = As[(m0 + 8 + gid) * LDA + kk + tig];
                a[mi][2] = As[(m0 + gid)     * LDA + kk + 4 + tig];
                a[mi][3] = As[(m0 + 8 + gid) * LDA + kk + 4 + tig];
            }
#pragma unroll
            for (int ni = 0; ni < 4; ni++) {
                int n0 = warp_n * 32 + ni * 8;
                b[ni][0] = Bs[(kk + tig)     * LDB + n0 + gid];
                b[ni][1] = Bs[(kk + 4 + tig) * LDB + n0 + gid];
            }
#pragma unroll
            for (int mi = 0; mi < 2; mi++)
#pragma unroll
                for (int ni = 0; ni < 4; ni++)
                    mma_tf32(acc[mi][ni], a[mi][0], a[mi][1], a[mi][2], a[mi][3],
                             b[ni][0], b[ni][1]);
        }
        __syncthreads();
    }

    // epilogue: bias + relu, store to g_x1
#pragma unroll
    for (int mi = 0; mi < 2; mi++) {
        int rbase = row0 + warp_m * 32 + mi * 16 + gid;
#pragma unroll
        for (int ni = 0; ni < 4; ni++) {
            int col = warp_n * 32 + ni * 8 + 2 * tig;
            float bb0 = __ldg(&b1[col]);
            float bb1 = __ldg(&b1[col + 1]);
            if (rbase < Nn) {
                float2 v;
                v.x = fmaxf(acc[mi][ni][0] + bb0, 0.f);
                v.y = fmaxf(acc[mi][ni][1] + bb1, 0.f);
                *(float2*)&g_x1[(size_t)rbase * NHID + col] = v;
            }
            if (rbase + 8 < Nn) {
                float2 v;
                v.x = fmaxf(acc[mi][ni][2] + bb0, 0.f);
                v.y = fmaxf(acc[mi][ni][3] + bb1, 0.f);
                *(float2*)&g_x1[(size_t)(rbase + 8) * NHID + col] = v;
            }
        }
    }
}

// ---------------- layer 2: h = x1 @ W2 + b2 --------------------------------
__global__ __launch_bounds__(256)
void mlp2_kernel(const float* __restrict__ W2, const float* __restrict__ b2)
{
    __shared__ float W2s[NHID * NCLS];
    __shared__ float b2s[NCLS];
    int tid = threadIdx.x;
    for (int i = tid; i < NHID * NCLS; i += 256) W2s[i] = W2[i];
    if (tid < NCLS) b2s[tid] = b2[tid];
    __syncthreads();

    int row = blockIdx.x * blockDim.x + tid;
    if (row >= Nn) return;

    float out[NCLS];
#pragma unroll
    for (int c = 0; c < NCLS; c++) out[c] = b2s[c];
    const float* xr = &g_x1[(size_t)row * NHID];
#pragma unroll 4
    for (int k0 = 0; k0 < NHID; k0 += 4) {
        float4 xv = *(const float4*)&xr[k0];
        float xs[4] = {xv.x, xv.y, xv.z, xv.w};
#pragma unroll
        for (int kk = 0; kk < 4; kk++)
#pragma unroll
            for (int c = 0; c < NCLS; c++)
                out[c] = fmaf(xs[kk], W2s[(k0 + kk) * NCLS + c], out[c]);
    }
    float4* hp = g_h + (size_t)row * 10;
#pragma unroll
    for (int q = 0; q < 10; q++)
        hp[q] = make_float4(out[4*q], out[4*q+1], out[4*q+2], out[4*q+3]);
}

// ---------------- CSR build ------------------------------------------------
__global__ void zero_kernel()
{
    int i = blockIdx.x * blockDim.x + threadIdx.x;
    if (i < Nn) g_counts[i] = 0;
    if (i < SCAN_NBLK) g_pub[i] = 0ull;
}

__global__ void hist_kernel(const int* __restrict__ rows)
{
    int j = blockIdx.x * blockDim.x + threadIdx.x;
    if (j < Ee / 4) {
        int4 r = ((const int4*)rows)[j];
        atomicAdd(&g_counts[r.x], 1);
        atomicAdd(&g_counts[r.y], 1);
        atomicAdd(&g_counts[r.z], 1);
        atomicAdd(&g_counts[r.w], 1);
    }
}

// single-pass decoupled-lookback exclusive scan
__global__ __launch_bounds__(SCAN_BLK)
void scan_kernel()
{
    __shared__ int swarp[32];
    __shared__ int s_prefix;
    __shared__ int s_total;

    const int b = blockIdx.x;
    const int t = threadIdx.x;
    const int lane = t & 31, wid = t >> 5;
    const int i = b * SCAN_BLK + t;

    int v = (i < Nn) ? g_counts[i] : 0;
    int incl = v;
#pragma unroll
    for (int off = 1; off < 32; off <<= 1) {
        int u = __shfl_up_sync(0xffffffffu, incl, off);
        if (lane >= off) incl += u;
    }
    if (lane == 31) swarp[wid] = incl;
    __syncthreads();
    if (wid == 0) {
        int w = swarp[lane];
        int wi = w;
#pragma unroll
        for (int off = 1; off < 32; off <<= 1) {
            int u = __shfl_up_sync(0xffffffffu, wi, off);
            if (lane >= off) wi += u;
        }
        swarp[lane] = wi - w;
        if (lane == 31) {
            int S = wi;
            s_total = S;
            if (b == 0) {
                atomicExch(&g_pub[0], (2ull << 32) | (unsigned)S);
                s_prefix = 0;
            } else {
                atomicExch(&g_pub[b], (1ull << 32) | (unsigned)S);
                long long run = 0;
                int p = b - 1;
                while (true) {
                    unsigned long long u =
                        *((volatile unsigned long long*)&g_pub[p]);
                    unsigned f = (unsigned)(u >> 32);
                    if (f == 2u) { run += (int)(unsigned)u; break; }
                    if (f == 1u) { run += (int)(unsigned)u; p--; }
                }
                atomicExch(&g_pub[b], (2ull << 32) | (unsigned)(run + S));
                s_prefix = (int)run;
            }
        }
    }
    __syncthreads();
    int pref = s_prefix;
    if (i < Nn) {
        int r = incl - v + swarp[wid] + pref;
        g_rowptr[i] = r;
        g_cursor[i] = r;
    }
    if (b == SCAN_NBLK - 1 && t == 0)
        g_rowptr[Nn] = pref + s_total;
}

__global__ void scatter_kernel(const int* __restrict__ rows,
                               const int* __restrict__ cols,
                               const float* __restrict__ vals)
{
    int j = blockIdx.x * blockDim.x + threadIdx.x;
    if (j < Ee / 4) {
        int4   r = ((const int4*)rows)[j];
        int4   c = ((const int4*)cols)[j];
        float4 v = ((const float4*)vals)[j];
        int p;
        p = atomicAdd(&g_cursor[r.x], 1); g_colval[p] = make_int2(c.x, __float_as_int(v.x));
        p = atomicAdd(&g_cursor[r.y], 1); g_colval[p] = make_int2(c.y, __float_as_int(v.y));
        p = atomicAdd(&g_cursor[r.z], 1); g_colval[p] = make_int2(c.z, __float_as_int(v.z));
        p = atomicAdd(&g_cursor[r.w], 1); g_colval[p] = make_int2(c.w, __float_as_int(v.w));
    }
}

// ---------------- propagation: x_out = 0.9 * A x_in + 0.1 * h --------------
__global__ __launch_bounds__(256)
void prop_kernel(int step)
{
    const float4* __restrict__ xin =
        (step == 0) ? g_h : ((step & 1) ? g_xa : g_xb);
    float4* __restrict__ xout = (step & 1) ? g_xb : g_xa;

    int t = blockIdx.x * blockDim.x + threadIdx.x;
    if (t >= Nn * 10) return;
    int node = t / 10;
    int g    = t - node * 10;

    int s = g_rowptr[node];
    int e = g_rowptr[node + 1];
    float4 a0 = make_float4(0.f, 0.f, 0.f, 0.f);
    float4 a1 = make_float4(0.f, 0.f, 0.f, 0.f);
    int i = s;
    for (; i + 2 <= e; i += 2) {
        int2 c0 = g_colval[i];
        int2 c1 = g_colval[i + 1];
        float4 x0 = __ldg(&xin[(size_t)c0.x * 10 + g]);
        float4 x1 = __ldg(&xin[(size_t)c1.x * 10 + g]);
        float v0 = __int_as_float(c0.y);
        float v1 = __int_as_float(c1.y);
        a0.x = fmaf(v0, x0.x, a0.x);  a1.x = fmaf(v1, x1.x, a1.x);
        a0.y = fmaf(v0, x0.y, a0.y);  a1.y = fmaf(v1, x1.y, a1.y);
        a0.z = fmaf(v0, x0.z, a0.z);  a1.z = fmaf(v1, x1.z, a1.z);
        a0.w = fmaf(v0, x0.w, a0.w);  a1.w = fmaf(v1, x1.w, a1.w);
    }
    if (i < e) {
        int2 c0 = g_colval[i];
        float4 x0 = __ldg(&xin[(size_t)c0.x * 10 + g]);
        float v0 = __int_as_float(c0.y);
        a0.x = fmaf(v0, x0.x, a0.x);
        a0.y = fmaf(v0, x0.y, a0.y);
        a0.z = fmaf(v0, x0.z, a0.z);
        a0.w = fmaf(v0, x0.w, a0.w);
    }
    float4 hv = g_h[t];
    float4 o;
    o.x = fmaf(0.9f, a0.x + a1.x, 0.1f * hv.x);
    o.y = fmaf(0.9f, a0.y + a1.y, 0.1f * hv.y);
    o.z = fmaf(0.9f, a0.z + a1.z, 0.1f * hv.z);
    o.w = fmaf(0.9f, a0.w + a1.w, 0.1f * hv.w);
    xout[t] = o;
}

// ---------------- log_softmax: warp per node -------------------------------
__global__ __launch_bounds__(256)
void logsoftmax_kernel(float* __restrict__ out)
{
    const float* __restrict__ x = (const float*)g_xb;   // step 9 output
    int warp = (blockIdx.x * blockDim.x + threadIdx.x) >> 5;
    int lane = threadIdx.x & 31;
    if (warp >= Nn) return;
    const float* xr = x + (size_t)warp * NCLS;
    float v0 = xr[lane];
    float v1 = (lane < 8) ? xr[32 + lane] : -INFINITY;
    float m = fmaxf(v0, v1);
#pragma unroll
    for (int off = 16; off > 0; off >>= 1)
        m = fmaxf(m, __shfl_xor_sync(0xffffffffu, m, off));
    float s = expf(v0 - m) + ((lane < 8) ? expf(v1 - m) : 0.f);
#pragma unroll
    for (int off = 16; off > 0; off >>= 1)
        s += __shfl_xor_sync(0xffffffffu, s, off);
    float lse = m + logf(s);
    float* o = out + (size_t)warp * NCLS;
    o[lane] = v0 - lse;
    if (lane < 8) o[32 + lane] = v1 - lse;
}

// ---------------- launch ---------------------------------------------------
extern "C" void kernel_launch(void* const* d_in, const int* in_sizes, int n_in,
                              void* d_out, int out_size)
{
    const float* feat = (const float*)d_in[0];
    const int*   ei   = (const int*)  d_in[1];
    const float* ev   = (const float*)d_in[2];
    const float* W1   = (const float*)d_in[3];
    const float* b1   = (const float*)d_in[4];
    const float* W2   = (const float*)d_in[5];
    const float* b2   = (const float*)d_in[6];
    const int* rows = ei;
    const int* cols = ei + Ee;

    zero_kernel<<<(Nn + 255) / 256, 256>>>();                           // 1
    hist_kernel<<<(Ee / 4 + 255) / 256, 256>>>(rows);                   // 2
    scan_kernel<<<SCAN_NBLK, SCAN_BLK>>>();                             // 3
    mlp1_kernel<<<(Nn + L1_BM - 1) / L1_BM, 256>>>(feat, W1, b1);       // 4 (profiled)
    scatter_kernel<<<(Ee / 4 + 255) / 256, 256>>>(rows, cols, ev);      // 5
    mlp2_kernel<<<(Nn + 255) / 256, 256>>>(W2, b2);                     // 6

    int pblocks = (Nn * 10 + 255) / 256;
    for (int s = 0; s < KSTEPS; s++)
        prop_kernel<<<pblocks, 256>>>(s);

    logsoftmax_kernel<<<(Nn * 32 + 255) / 256, 256>>>((float*)d_out);
}

// round 5
// speedup vs baseline: 1.5970x; 1.0736x over previous
#include <cuda_runtime.h>
#include <math.h>

#define Nn 100000
#define Ee 3200000
#define FIN 512
#define NHID 64
#define NCLS 40
#define KSTEPS 10

// ---------------- scratch (static device globals — no allocation) ----------
__device__ float4 g_h [Nn * 10];   // teleport term, [N][40] as float4[N][10]
__device__ float4 g_xa[Nn * 10];   // ping
__device__ float4 g_xb[Nn * 10];   // pong
__device__ float  g_x1[(size_t)Nn * NHID];  // layer-1 activations
__device__ int    g_counts[Nn];
__device__ int    g_rowptr[Nn + 1];
__device__ int    g_cursor[Nn];
__device__ int2   g_colval[Ee];    // interleaved {col, val-bits}

#define SCAN_BLK  1024
#define SCAN_NBLK ((Nn + SCAN_BLK - 1) / SCAN_BLK)   // 98
__device__ unsigned long long g_pub[SCAN_NBLK];      // packed {flag,sum}

// ---------------- layer 1: x1 = relu(X@W1 + b1) via tf32 mma ---------------
// BM=128, BN=64, BK=16, 2-stage cp.async pipeline. 8 warps; warp tile 32x32.
#define L1_BM 128
#define L1_BK 16
#define NTILE (FIN / L1_BK)   // 32
#define LDA   20    // As[m][k] floats; (20m+k)%32 conflict-free frag reads
#define LDB   72    // Bs[k][n] floats; (72k+n)%32=(8k+n)%32 conflict-free

__device__ __forceinline__ unsigned f2tf32(float f) {
    unsigned r;
    asm("cvt.rna.tf32.f32 %0, %1;" : "=r"(r) : "f"(f));
    return r;
}

__device__ __forceinline__ void mma_tf32(float* c, unsigned a0, unsigned a1,
                                         unsigned a2, unsigned a3,
                                         unsigned b0, unsigned b1) {
    asm volatile(
        "mma.sync.aligned.m16n8k8.row.col.f32.tf32.tf32.f32 "
        "{%0,%1,%2,%3}, {%4,%5,%6,%7}, {%8,%9}, {%0,%1,%2,%3};\n"
        : "+f"(c[0]), "+f"(c[1]), "+f"(c[2]), "+f"(c[3])
        : "r"(a0), "r"(a1), "r"(a2), "r"(a3), "r"(b0), "r"(b1));
}

__device__ __forceinline__ void cp16(float* smem_dst, const float* gsrc, bool pred) {
    unsigned saddr = (unsigned)__cvta_generic_to_shared(smem_dst);
    int sz = pred ? 16 : 0;
    asm volatile("cp.async.cg.shared.global [%0], [%1], 16, %2;\n"
                 :: "r"(saddr), "l"(gsrc), "r"(sz));
}

__global__ __launch_bounds__(256, 3)
void mlp1_kernel(const float* __restrict__ feat,
                 const float* __restrict__ W1, const float* __restrict__ b1)
{
    __shared__ __align__(16) float As[2][L1_BM * LDA];   // 2*128*20*4 = 20480 B
    __shared__ __align__(16) float Bs[2][L1_BK * LDB];   // 2*16*72*4  =  9216 B

    const int tid    = threadIdx.x;
    const int lane   = tid & 31;
    const int warp   = tid >> 5;
    const int warp_m = warp & 3;           // 0..3  (32 rows each)
    const int warp_n = warp >> 2;          // 0..1  (32 cols each)
    const int gid    = lane >> 2;          // 0..7
    const int tig    = lane & 3;           // 0..3
    const int row0   = blockIdx.x * L1_BM;

    // staging indices (per thread): A = 2 chunks, B = 1 chunk per tile
    const int am0 = tid >> 2;              // row for chunk 0 (0..63)
    const int ac0 = tid & 3;               // float4 col
    const int am1 = (tid + 256) >> 2;      // row for chunk 1 (64..127)
    const int bk  = tid >> 4;              // 0..15
    const int bn  = tid & 15;              // 0..15

    float acc[2][4][4];
#pragma unroll
    for (int mi = 0; mi < 2; mi++)
#pragma unroll
        for (int ni = 0; ni < 4; ni++)
#pragma unroll
            for (int q = 0; q < 4; q++) acc[mi][ni][q] = 0.f;

    // stage tile t into buffer buf
    auto stage = [&](int t, int buf) {
        int k0 = t * L1_BK;
        cp16(&As[buf][am0 * LDA + ac0 * 4],
             &feat[(size_t)(row0 + am0) * FIN + k0 + ac0 * 4], row0 + am0 < Nn);
        cp16(&As[buf][am1 * LDA + ac0 * 4],
             &feat[(size_t)(row0 + am1) * FIN + k0 + ac0 * 4], row0 + am1 < Nn);
        cp16(&Bs[buf][bk * LDB + bn * 4],
             &W1[(size_t)(k0 + bk) * NHID + bn * 4], true);
        asm volatile("cp.async.commit_group;\n");
    };

    stage(0, 0);

    for (int t = 0; t < NTILE; t++) {
        if (t + 1 < NTILE) {
            stage(t + 1, (t + 1) & 1);
            asm volatile("cp.async.wait_group 1;\n");
        } else {
            asm volatile("cp.async.wait_group 0;\n");
        }
        __syncthreads();

        const float* A = As[t & 1];
        const float* B = Bs[t & 1];
#pragma unroll
        for (int kk = 0; kk < L1_BK; kk += 8) {
            unsigned a[2][4], b[4][2];
#pragma unroll
            for (int mi = 0; mi < 2; mi++) {
                int m0 = warp_m * 32 + mi * 16;
                a[mi][0] = f2tf32(A[(m0 + gid)     * LDA + kk + tig]);
                a[mi][1] = f2tf32(A[(m0 + 8 + gid) * LDA + kk + tig]);
                a[mi][2] = f2tf32(A[(m0 + gid)     * LDA + kk + 4 + tig]);
                a[mi][3] = f2tf32(A[(m0 + 8 + gid) * LDA + kk + 4 + tig]);
            }
#pragma unroll
            for (int ni = 0; ni < 4; ni++) {
                int n0 = warp_n * 32 + ni * 8;
                b[ni][0] = f2tf32(B[(kk + tig)     * LDB + n0 + gid]);
                b[ni][1] = f2tf32(B[(kk + 4 + tig) * LDB + n0 + gid]);
            }
#pragma unroll
            for (int mi = 0; mi < 2; mi++)
#pragma unroll
                for (int ni = 0; ni < 4; ni++)
                    mma_tf32(acc[mi][ni], a[mi][0], a[mi][1], a[mi][2], a[mi][3],
                             b[ni][0], b[ni][1]);
        }
        __syncthreads();
    }

    // epilogue: bias + relu, store to g_x1
#pragma unroll
    for (int mi = 0; mi < 2; mi++) {
        int rbase = row0 + warp_m * 32 + mi * 16 + gid;
#pragma unroll
        for (int ni = 0; ni < 4; ni++) {
            int col = warp_n * 32 + ni * 8 + 2 * tig;
            float bb0 = __ldg(&b1[col]);
            float bb1 = __ldg(&b1[col + 1]);
            if (rbase < Nn) {
                float2 v;
                v.x = fmaxf(acc[mi][ni][0] + bb0, 0.f);
                v.y = fmaxf(acc[mi][ni][1] + bb1, 0.f);
                *(float2*)&g_x1[(size_t)rbase * NHID + col] = v;
            }
            if (rbase + 8 < Nn) {
                float2 v;
                v.x = fmaxf(acc[mi][ni][2] + bb0, 0.f);
                v.y = fmaxf(acc[mi][ni][3] + bb1, 0.f);
                *(float2*)&g_x1[(size_t)(rbase + 8) * NHID + col] = v;
            }
        }
    }
}

// ---------------- layer 2: h = x1 @ W2 + b2 --------------------------------
__global__ __launch_bounds__(256)
void mlp2_kernel(const float* __restrict__ W2, const float* __restrict__ b2)
{
    __shared__ float W2s[NHID * NCLS];
    __shared__ float b2s[NCLS];
    int tid = threadIdx.x;
    for (int i = tid; i < NHID * NCLS; i += 256) W2s[i] = W2[i];
    if (tid < NCLS) b2s[tid] = b2[tid];
    __syncthreads();

    int row = blockIdx.x * blockDim.x + tid;
    if (row >= Nn) return;

    float out[NCLS];
#pragma unroll
    for (int c = 0; c < NCLS; c++) out[c] = b2s[c];
    const float* xr = &g_x1[(size_t)row * NHID];
#pragma unroll 4
    for (int k0 = 0; k0 < NHID; k0 += 4) {
        float4 xv = *(const float4*)&xr[k0];
        float xs[4] = {xv.x, xv.y, xv.z, xv.w};
#pragma unroll
        for (int kk = 0; kk < 4; kk++)
#pragma unroll
            for (int c = 0; c < NCLS; c++)
                out[c] = fmaf(xs[kk], W2s[(k0 + kk) * NCLS + c], out[c]);
    }
    float4* hp = g_h + (size_t)row * 10;
#pragma unroll
    for (int q = 0; q < 10; q++)
        hp[q] = make_float4(out[4*q], out[4*q+1], out[4*q+2], out[4*q+3]);
}

// ---------------- CSR build ------------------------------------------------
__global__ void zero_kernel()
{
    int i = blockIdx.x * blockDim.x + threadIdx.x;
    if (i < Nn) g_counts[i] = 0;
    if (i < SCAN_NBLK) g_pub[i] = 0ull;
}

__global__ void hist_kernel(const int* __restrict__ rows)
{
    int j = blockIdx.x * blockDim.x + threadIdx.x;
    if (j < Ee / 4) {
        int4 r = ((const int4*)rows)[j];
        atomicAdd(&g_counts[r.x], 1);
        atomicAdd(&g_counts[r.y], 1);
        atomicAdd(&g_counts[r.z], 1);
        atomicAdd(&g_counts[r.w], 1);
    }
}

// single-pass decoupled-lookback exclusive scan
__global__ __launch_bounds__(SCAN_BLK)
void scan_kernel()
{
    __shared__ int swarp[32];
    __shared__ int s_prefix;
    __shared__ int s_total;

    const int b = blockIdx.x;
    const int t = threadIdx.x;
    const int lane = t & 31, wid = t >> 5;
    const int i = b * SCAN_BLK + t;

    int v = (i < Nn) ? g_counts[i] : 0;
    int incl = v;
#pragma unroll
    for (int off = 1; off < 32; off <<= 1) {
        int u = __shfl_up_sync(0xffffffffu, incl, off);
        if (lane >= off) incl += u;
    }
    if (lane == 31) swarp[wid] = incl;
    __syncthreads();
    if (wid == 0) {
        int w = swarp[lane];
        int wi = w;
#pragma unroll
        for (int off = 1; off < 32; off <<= 1) {
            int u = __shfl_up_sync(0xffffffffu, wi, off);
            if (lane >= off) wi += u;
        }
        swarp[lane] = wi - w;
        if (lane == 31) {
            int S = wi;
            s_total = S;
            if (b == 0) {
                atomicExch(&g_pub[0], (2ull << 32) | (unsigned)S);
                s_prefix = 0;
            } else {
                atomicExch(&g_pub[b], (1ull << 32) | (unsigned)S);
                long long run = 0;
                int p = b - 1;
                while (true) {
                    unsigned long long u =
                        *((volatile unsigned long long*)&g_pub[p]);
                    unsigned f = (unsigned)(u >> 32);
                    if (f == 2u) { run += (int)(unsigned)u; break; }
                    if (f == 1u) { run += (int)(unsigned)u; p--; }
                }
                atomicExch(&g_pub[b], (2ull << 32) | (unsigned)(run + S));
                s_prefix = (int)run;
            }
        }
    }
    __syncthreads();
    int pref = s_prefix;
    if (i < Nn) {
        int r = incl - v + swarp[wid] + pref;
        g_rowptr[i] = r;
        g_cursor[i] = r;
    }
    if (b == SCAN_NBLK - 1 && t == 0)
        g_rowptr[Nn] = pref + s_total;
}

__global__ void scatter_kernel(const int* __restrict__ rows,
                               const int* __restrict__ cols,
                               const float* __restrict__ vals)
{
    int j = blockIdx.x * blockDim.x + threadIdx.x;
    if (j < Ee / 4) {
        int4   r = ((const int4*)rows)[j];
        int4   c = ((const int4*)cols)[j];
        float4 v = ((const float4*)vals)[j];
        int p;
        p = atomicAdd(&g_cursor[r.x], 1); g_colval[p] = make_int2(c.x, __float_as_int(v.x));
        p = atomicAdd(&g_cursor[r.y], 1); g_colval[p] = make_int2(c.y, __float_as_int(v.y));
        p = atomicAdd(&g_cursor[r.z], 1); g_colval[p] = make_int2(c.z, __float_as_int(v.z));
        p = atomicAdd(&g_cursor[r.w], 1); g_colval[p] = make_int2(c.w, __float_as_int(v.w));
    }
}

// ---------------- propagation: x_out = 0.9 * A x_in + 0.1 * h --------------
__global__ __launch_bounds__(256)
void prop_kernel(int step)
{
    const float4* __restrict__ xin =
        (step == 0) ? g_h : ((step & 1) ? g_xa : g_xb);
    float4* __restrict__ xout = (step & 1) ? g_xb : g_xa;

    int t = blockIdx.x * blockDim.x + threadIdx.x;
    if (t >= Nn * 10) return;
    int node = t / 10;
    int g    = t - node * 10;

    int s = g_rowptr[node];
    int e = g_rowptr[node + 1];
    float4 a0 = make_float4(0.f, 0.f, 0.f, 0.f);
    float4 a1 = make_float4(0.f, 0.f, 0.f, 0.f);
    int i = s;
    for (; i + 2 <= e; i += 2) {
        int2 c0 = g_colval[i];
        int2 c1 = g_colval[i + 1];
        float4 x0 = __ldg(&xin[(size_t)c0.x * 10 + g]);
        float4 x1 = __ldg(&xin[(size_t)c1.x * 10 + g]);
        float v0 = __int_as_float(c0.y);
        float v1 = __int_as_float(c1.y);
        a0.x = fmaf(v0, x0.x, a0.x);  a1.x = fmaf(v1, x1.x, a1.x);
        a0.y = fmaf(v0, x0.y, a0.y);  a1.y = fmaf(v1, x1.y, a1.y);
        a0.z = fmaf(v0, x0.z, a0.z);  a1.z = fmaf(v1, x1.z, a1.z);
        a0.w = fmaf(v0, x0.w, a0.w);  a1.w = fmaf(v1, x1.w, a1.w);
    }
    if (i < e) {
        int2 c0 = g_colval[i];
        float4 x0 = __ldg(&xin[(size_t)c0.x * 10 + g]);
        float v0 = __int_as_float(c0.y);
        a0.x = fmaf(v0, x0.x, a0.x);
        a0.y = fmaf(v0, x0.y, a0.y);
        a0.z = fmaf(v0, x0.z, a0.z);
        a0.w = fmaf(v0, x0.w, a0.w);
    }
    float4 hv = g_h[t];
    float4 o;
    o.x = fmaf(0.9f, a0.x + a1.x, 0.1f * hv.x);
    o.y = fmaf(0.9f, a0.y + a1.y, 0.1f * hv.y);
    o.z = fmaf(0.9f, a0.z + a1.z, 0.1f * hv.z);
    o.w = fmaf(0.9f, a0.w + a1.w, 0.1f * hv.w);
    xout[t] = o;
}

// ---------------- log_softmax: warp per node -------------------------------
__global__ __launch_bounds__(256)
void logsoftmax_kernel(float* __restrict__ out)
{
    const float* __restrict__ x = (const float*)g_xb;   // step 9 output
    int warp = (blockIdx.x * blockDim.x + threadIdx.x) >> 5;
    int lane = threadIdx.x & 31;
    if (warp >= Nn) return;
    const float* xr = x + (size_t)warp * NCLS;
    float v0 = xr[lane];
    float v1 = (lane < 8) ? xr[32 + lane] : -INFINITY;
    float m = fmaxf(v0, v1);
#pragma unroll
    for (int off = 16; off > 0; off >>= 1)
        m = fmaxf(m, __shfl_xor_sync(0xffffffffu, m, off));
    float s = expf(v0 - m) + ((lane < 8) ? expf(v1 - m) : 0.f);
#pragma unroll
    for (int off = 16; off > 0; off >>= 1)
        s += __shfl_xor_sync(0xffffffffu, s, off);
    float lse = m + logf(s);
    float* o = out + (size_t)warp * NCLS;
    o[lane] = v0 - lse;
    if (lane < 8) o[32 + lane] = v1 - lse;
}

// ---------------- launch ---------------------------------------------------
static cudaStream_t get_side_stream()
{
    static cudaStream_t s = []() {
        cudaStream_t st;
        cudaStreamCreateWithFlags(&st, cudaStreamNonBlocking);
        return st;
    }();
    return s;
}
static cudaEvent_t get_ev(int which)
{
    static cudaEvent_t e0 = []() {
        cudaEvent_t e; cudaEventCreateWithFlags(&e, cudaEventDisableTiming); return e;
    }();
    static cudaEvent_t e1 = []() {
        cudaEvent_t e; cudaEventCreateWithFlags(&e, cudaEventDisableTiming); return e;
    }();
    return which ? e1 : e0;
}

extern "C" void kernel_launch(void* const* d_in, const int* in_sizes, int n_in,
                              void* d_out, int out_size)
{
    const float* feat = (const float*)d_in[0];
    const int*   ei   = (const int*)  d_in[1];
    const float* ev   = (const float*)d_in[2];
    const float* W1   = (const float*)d_in[3];
    const float* b1   = (const float*)d_in[4];
    const float* W2   = (const float*)d_in[5];
    const float* b2   = (const float*)d_in[6];
    const int* rows = ei;
    const int* cols = ei + Ee;

    cudaStream_t s2 = get_side_stream();
    cudaEvent_t eva = get_ev(0), evb = get_ev(1);

    // fork side stream off the main (capturing) stream
    cudaEventRecord(eva, 0);
    cudaStreamWaitEvent(s2, eva, 0);

    // side stream: CSR build chain (launches 1-3, then 5)
    zero_kernel<<<(Nn + 255) / 256, 256, 0, s2>>>();
    hist_kernel<<<(Ee / 4 + 255) / 256, 256, 0, s2>>>(rows);
    scan_kernel<<<SCAN_NBLK, SCAN_BLK, 0, s2>>>();

    // main stream: MLP chain (launch 4 = mlp1, profiled)
    mlp1_kernel<<<(Nn + L1_BM - 1) / L1_BM, 256>>>(feat, W1, b1);

    scatter_kernel<<<(Ee / 4 + 255) / 256, 256, 0, s2>>>(rows, cols, ev);

    mlp2_kernel<<<(Nn + 255) / 256, 256>>>(W2, b2);

    // join: main stream waits for CSR chain
    cudaEventRecord(evb, s2);
    cudaStreamWaitEvent(0, evb, 0);

    int pblocks = (Nn * 10 + 255) / 256;
    for (int s = 0; s < KSTEPS; s++)
        prop_kernel<<<pblocks, 256>>>(s);

    logsoftmax_kernel<<<(Nn * 32 + 255) / 256, 256>>>((float*)d_out);
}